// round 16
// baseline (speedup 1.0000x reference)
#include <cuda_runtime.h>
#include <cuda_bf16.h>
#include <mma.h>
#include <math.h>
#include <stdint.h>

using namespace nvcuda;

#define BB 4
#define LL 1024
#define HH 768
#define NHH 12
#define EE 32
#define MPE 4
#define EMM 128
#define KLNK 16
#define TYPED 20
#define NROWS 336
#define FF 788
#define NA 160
#define NSPLIT 6

// scratch
__device__ uint32_t g_ahi[BB * EMM * 512];                   // mention rows bf16x2 hi
__device__ uint32_t g_alo[BB * EMM * 512];                   // residual lo
__device__ float    g_rs[BB * EMM];                          // exact fp32 row sums
__device__ float    g_part[(size_t)NSPLIT * BB * EMM * HH];  // split-K partials
__device__ int      g_cnt[BB * 12];                          // completion counters

__device__ __forceinline__ uint32_t packbf(float lo, float hi) {
    uint32_t r;
    asm("cvt.rn.bf16x2.f32 %0, %1, %2;" : "=r"(r) : "f"(hi), "f"(lo));
    return r;
}
__device__ __forceinline__ float bflo(uint32_t p) { return __uint_as_float(p << 16); }
__device__ __forceinline__ float bfhi(uint32_t p) { return __uint_as_float(p & 0xFFFF0000u); }

// ---------------------------------------------------------------------------
// K1 "front": link [0,64) + mention rows [64,576). 576 blocks = 1 wave.
// ---------------------------------------------------------------------------
__global__ void __launch_bounds__(256) k_front(
    const float* __restrict__ att, const float* __restrict__ seq,
    const float* __restrict__ ttab, const int* __restrict__ mpos,
    const int* __restrict__ lstart, const int* __restrict__ llen,
    float* __restrict__ out)
{
    __shared__ float part[32][33];
    __shared__ float wsh[32];
    __shared__ float red[8];
    int bid = blockIdx.x, tid = threadIdx.x;

    if (bid < 64) {
        int k = bid & 15, b = bid >> 4;
        int s = lstart[b * KLNK + k] + 1;
        int len = llen[b * KLNK + k] + 1;
        int r = tid >> 3, c4 = (tid & 7) * 4;
        float a0 = 0.f, a1 = 0.f, a2 = 0.f, a3 = 0.f;
        if (r < len) {
            const float* base = att + (size_t)b * NHH * LL * LL + (size_t)(s + r) * LL + s + c4;
#pragma unroll
            for (int h = 0; h < NHH; h++) {
                const float* p = base + (size_t)h * LL * LL;
                a0 += p[0]; a1 += p[1]; a2 += p[2]; a3 += p[3];
            }
        }
        if (c4 + 0 >= len) a0 = 0.f;
        if (c4 + 1 >= len) a1 = 0.f;
        if (c4 + 2 >= len) a2 = 0.f;
        if (c4 + 3 >= len) a3 = 0.f;
        part[r][c4] = a0; part[r][c4 + 1] = a1; part[r][c4 + 2] = a2; part[r][c4 + 3] = a3;
        __syncthreads();
        if (tid < 32) {
            float sum = 0.f;
#pragma unroll
            for (int rr = 0; rr < 32; rr++) sum += part[rr][tid];   // fixed order
            wsh[tid] = sum;
        }
        __syncthreads();
        float scale = 1.f / (12.f * (float)len);
        const float* sq = seq + ((size_t)b * LL + s) * HH;
        float* o = out + ((size_t)b * NROWS + 160 + k) * FF;
        for (int f = tid; f < HH; f += 256) {
            float b0 = 0.f, b1 = 0.f, b2 = 0.f, b3 = 0.f;
#pragma unroll
            for (int c = 0; c < 32; c += 4) {
                b0 += wsh[c] * sq[(size_t)c * HH + f];
                b1 += wsh[c + 1] * sq[(size_t)(c + 1) * HH + f];
                b2 += wsh[c + 2] * sq[(size_t)(c + 2) * HH + f];
                b3 += wsh[c + 3] * sq[(size_t)(c + 3) * HH + f];
            }
            o[f] = ((b0 + b1) + (b2 + b3)) * scale;
        }
        if (tid < TYPED) o[HH + tid] = ttab[2 * TYPED + tid];
    } else {
        int i = bid - 64;
        int m = i & 127, b = i >> 7;
        int p = mpos[b * EMM + m] + 1;
        const float* rp = att + (size_t)b * NHH * LL * LL + (size_t)p * LL + tid * 4;
        float4 a = make_float4(0.f, 0.f, 0.f, 0.f);
#pragma unroll
        for (int h = 0; h < NHH; h++) {
            float4 v = *(const float4*)(rp + (size_t)h * LL * LL);
            a.x += v.x; a.y += v.y; a.z += v.z; a.w += v.w;
        }
        const float iv = 1.f / 12.f;
        a.x *= iv; a.y *= iv; a.z *= iv; a.w *= iv;
        uint32_t h1 = packbf(a.x, a.y), h2 = packbf(a.z, a.w);
        uint32_t l1 = packbf(a.x - bflo(h1), a.y - bfhi(h1));
        uint32_t l2 = packbf(a.z - bflo(h2), a.w - bfhi(h2));
        size_t u = ((size_t)b * EMM + m) * 512 + tid * 2;
        *(uint2*)&g_ahi[u] = make_uint2(h1, h2);
        *(uint2*)&g_alo[u] = make_uint2(l1, l2);

        float s = (a.x + a.y) + (a.z + a.w);
#pragma unroll
        for (int o = 16; o > 0; o >>= 1) s += __shfl_down_sync(0xffffffffu, s, o);
        if ((tid & 31) == 0) red[tid >> 5] = s;
        __syncthreads();
        if (tid == 0) {
            float t = 0.f;
#pragma unroll
            for (int w = 0; w < 8; w++) t += red[w];               // fixed order
            g_rs[b * EMM + m] = t;
        }
    }
}

// ---------------------------------------------------------------------------
// K2: GEMM blocks [0,288) (WMMA bf16 3-pass, 128m x 64h, fused last-block
// epilogue per (b,hb)) + node blocks [288,928).
// ---------------------------------------------------------------------------
#define LDA 40
#define LDB 72
#define CTX_SMEM 59392
__global__ void __launch_bounds__(256, 2) k_ctx_w(
    const float* __restrict__ seq, const float* __restrict__ ttab,
    const int* __restrict__ mpos, float* __restrict__ out)
{
    extern __shared__ __align__(16) char dyn[];
    __shared__ int sLast;
    int bid = blockIdx.x, tid = threadIdx.x;

    if (bid >= 288) {
        // ------------------------- node bank rows 0..159 --------------------
        int i = bid - 288;
        int r2 = i % 160, b = i / 160;
        float* o = out + ((size_t)b * NROWS + r2) * FF;
        if (r2 < EE) {
            const int* mp = mpos + (b * EE + r2) * MPE;
            int p0 = mp[0] + 1, p1 = mp[1] + 1, p2 = mp[2] + 1, p3 = mp[3] + 1;
            if (tid < 192) {
                int f = tid * 4;
                float4 x0 = *(const float4*)(seq + ((size_t)b * LL + p0) * HH + f);
                float4 x1 = *(const float4*)(seq + ((size_t)b * LL + p1) * HH + f);
                float4 x2 = *(const float4*)(seq + ((size_t)b * LL + p2) * HH + f);
                float4 x3 = *(const float4*)(seq + ((size_t)b * LL + p3) * HH + f);
                float4 res;
                float m0 = fmaxf(fmaxf(x0.x, x1.x), fmaxf(x2.x, x3.x));
                res.x = m0 + logf(expf(x0.x-m0)+expf(x1.x-m0)+expf(x2.x-m0)+expf(x3.x-m0));
                float m1 = fmaxf(fmaxf(x0.y, x1.y), fmaxf(x2.y, x3.y));
                res.y = m1 + logf(expf(x0.y-m1)+expf(x1.y-m1)+expf(x2.y-m1)+expf(x3.y-m1));
                float m2 = fmaxf(fmaxf(x0.z, x1.z), fmaxf(x2.z, x3.z));
                res.z = m2 + logf(expf(x0.z-m2)+expf(x1.z-m2)+expf(x2.z-m2)+expf(x3.z-m2));
                float m3 = fmaxf(fmaxf(x0.w, x1.w), fmaxf(x2.w, x3.w));
                res.w = m3 + logf(expf(x0.w-m3)+expf(x1.w-m3)+expf(x2.w-m3)+expf(x3.w-m3));
                *(float4*)(o + f) = res;
            } else if (tid < 192 + TYPED) {
                o[HH + tid - 192] = ttab[tid - 192];
            }
        } else {
            int m = r2 - EE;
            int p = mpos[b * EMM + m] + 1;
            if (tid < 192)
                *(float4*)(o + tid * 4) = *(const float4*)(seq + ((size_t)b * LL + p) * HH + tid * 4);
            else if (tid < 192 + TYPED)
                o[HH + tid - 192] = ttab[TYPED + tid - 192];
        }
        return;
    }

    // ---------------------------- GEMM block --------------------------------
    int s = bid / 48;
    int rem = bid % 48;
    int hb = rem % 12, b = rem / 12;
    int h0 = hb * 64;
    int l_start = (s < 2) ? s * 192 : 384 + (s - 2) * 160;
    int stages = (s < 2) ? 6 : 5;
    int wid = tid >> 5;
    int wm = (wid & 3) * 32, wn = (wid >> 2) * 32;

    __nv_bfloat16* SAh = (__nv_bfloat16*)dyn;
    __nv_bfloat16* SAl = SAh + 10240;
    __nv_bfloat16* SBh = SAl + 10240;
    __nv_bfloat16* SBl = SBh + 4608;

    const uint32_t* ahi = g_ahi + (size_t)b * EMM * 512;
    const uint32_t* alo = g_alo + (size_t)b * EMM * 512;
    const float* seqb = seq + (size_t)b * LL * HH;

    wmma::fragment<wmma::accumulator, 16, 16, 16, float> acc[2][2];
#pragma unroll
    for (int i = 0; i < 2; i++)
#pragma unroll
        for (int j = 0; j < 2; j++) wmma::fill_fragment(acc[i][j], 0.f);

    auto loadA = [&](int buf, int k0) {
        uint32_t* ah = (uint32_t*)(SAh + buf * 5120);
        uint32_t* al = (uint32_t*)(SAl + buf * 5120);
        int kb = k0 >> 1;
#pragma unroll
        for (int it = 0; it < 4; it++) {
            int idx = tid + it * 256;
            int m = idx >> 3, u = (idx & 7) * 2;
            uint2 vh = *(const uint2*)(ahi + (size_t)m * 512 + kb + u);
            uint2 vl = *(const uint2*)(alo + (size_t)m * 512 + kb + u);
            *(uint2*)(ah + m * (LDA / 2) + u) = vh;
            *(uint2*)(al + m * (LDA / 2) + u) = vl;
        }
    };
    auto loadB = [&](int buf, int k0) {
        __nv_bfloat16* bh = SBh + buf * 2304;
        __nv_bfloat16* bl = SBl + buf * 2304;
#pragma unroll
        for (int it = 0; it < 2; it++) {
            int idx = tid + it * 256;
            int k = idx >> 4, h4 = (idx & 15) * 4;
            float4 v = *(const float4*)&seqb[(size_t)(k0 + k) * HH + h0 + h4];
            uint32_t h1 = packbf(v.x, v.y), h2 = packbf(v.z, v.w);
            uint32_t l1 = packbf(v.x - bflo(h1), v.y - bfhi(h1));
            uint32_t l2 = packbf(v.z - bflo(h2), v.w - bfhi(h2));
            *(uint2*)(bh + k * LDB + h4) = make_uint2(h1, h2);
            *(uint2*)(bl + k * LDB + h4) = make_uint2(l1, l2);
        }
    };

    loadA(0, l_start);
    loadB(0, l_start);
    __syncthreads();

    for (int st = 0; st < stages; st++) {
        int cur = st & 1;
        if (st + 1 < stages) {
            loadA(cur ^ 1, l_start + (st + 1) * 32);
            loadB(cur ^ 1, l_start + (st + 1) * 32);
        }
#pragma unroll
        for (int kk = 0; kk < 2; kk++) {
            wmma::fragment<wmma::matrix_a, 16, 16, 16, __nv_bfloat16, wmma::row_major> fah[2], fal[2];
            wmma::fragment<wmma::matrix_b, 16, 16, 16, __nv_bfloat16, wmma::row_major> fbh[2], fbl[2];
#pragma unroll
            for (int i = 0; i < 2; i++) {
                wmma::load_matrix_sync(fah[i], SAh + cur * 5120 + (wm + i * 16) * LDA + kk * 16, LDA);
                wmma::load_matrix_sync(fal[i], SAl + cur * 5120 + (wm + i * 16) * LDA + kk * 16, LDA);
            }
#pragma unroll
            for (int j = 0; j < 2; j++) {
                wmma::load_matrix_sync(fbh[j], SBh + cur * 2304 + kk * 16 * LDB + wn + j * 16, LDB);
                wmma::load_matrix_sync(fbl[j], SBl + cur * 2304 + kk * 16 * LDB + wn + j * 16, LDB);
            }
#pragma unroll
            for (int i = 0; i < 2; i++)
#pragma unroll
                for (int j = 0; j < 2; j++) {
                    wmma::mma_sync(acc[i][j], fah[i], fbh[j], acc[i][j]);
                    wmma::mma_sync(acc[i][j], fal[i], fbh[j], acc[i][j]);
                    wmma::mma_sync(acc[i][j], fah[i], fbl[j], acc[i][j]);
                }
        }
        __syncthreads();
    }

#pragma unroll
    for (int i = 0; i < 2; i++)
#pragma unroll
        for (int j = 0; j < 2; j++) {
            float* dst = g_part + (((size_t)s * BB + b) * EMM + wm + i * 16) * HH
                       + h0 + wn + j * 16;
            wmma::store_matrix_sync(dst, acc[i][j], HH, wmma::mem_row_major);
        }

    // ---- last-block fused epilogue for (b, hb) ----
    __threadfence();
    __syncthreads();
    if (tid == 0) {
        int old = atomicAdd(&g_cnt[b * 12 + hb], 1);
        sLast = (old == NSPLIT - 1);
    }
    __syncthreads();
    if (!sLast) return;
    if (tid == 0) g_cnt[b * 12 + hb] = 0;   // reset for next graph replay
    __threadfence();

    const size_t SP = (size_t)BB * EMM * HH;
    float* MS = (float*)dyn;                 // [128][64], reuses GEMM smem
#pragma unroll
    for (int it = 0; it < 32; it++) {
        int idx = tid + it * 256;
        int m = idx >> 6, hl = idx & 63;
        const float* gp = g_part + ((size_t)b * EMM + m) * HH + h0 + hl;
        float sum = 0.f;
#pragma unroll
        for (int s2 = 0; s2 < NSPLIT; s2++)              // fixed order
            sum += __ldcg(gp + s2 * SP);
        MS[idx] = sum;
    }
    __syncthreads();

    int hl = tid & 63, rg = tid >> 6;        // 4 row-groups
    for (int r = rg; r < NA; r += 4) {
        float v, scale;
        if (r < EE) {
            int m4 = r * 4;
            v = (MS[m4 * 64 + hl] + MS[(m4 + 1) * 64 + hl])
              + (MS[(m4 + 2) * 64 + hl] + MS[(m4 + 3) * 64 + hl]);
            const float* rs = g_rs + b * EMM + m4;
            scale = 1.f / ((((rs[0] + rs[1]) + rs[2]) + rs[3]) + 4e-5f);
        } else {
            v = MS[(r - EE) * 64 + hl];
            scale = 1.f / (g_rs[b * EMM + r - EE] + 1e-5f);
        }
        out[((size_t)b * NROWS + 176 + r) * FF + h0 + hl] = v * scale;
    }
    if (hb == 11) {                          // zero type pad for ctx rows
        for (int z = tid; z < NA * TYPED; z += 256)
            out[((size_t)b * NROWS + 176 + z / TYPED) * FF + HH + z % TYPED] = 0.f;
    }
}

// ---------------------------------------------------------------------------
extern "C" void kernel_launch(void* const* d_in, const int* in_sizes, int n_in,
                              void* d_out, int out_size) {
    const float* seq    = (const float*)d_in[0];
    const float* att    = (const float*)d_in[1];
    const float* ttab   = (const float*)d_in[2];
    const int*   mpos   = (const int*)d_in[3];
    const int*   lstart = (const int*)d_in[4];
    const int*   llen   = (const int*)d_in[5];
    float* out = (float*)d_out;

    cudaFuncSetAttribute(k_ctx_w, cudaFuncAttributeMaxDynamicSharedMemorySize,
                         CTX_SMEM);

    k_front<<<64 + 512, 256>>>(att, seq, ttab, mpos, lstart, llen, out);
    k_ctx_w<<<288 + 640, 256, CTX_SMEM>>>(seq, ttab, mpos, out);
}

// round 17
// speedup vs baseline: 1.2358x; 1.2358x over previous
#include <cuda_runtime.h>
#include <cuda_bf16.h>
#include <mma.h>
#include <math.h>
#include <stdint.h>

using namespace nvcuda;

#define BB 4
#define LL 1024
#define HH 768
#define NHH 12
#define EE 32
#define MPE 4
#define EMM 128
#define KLNK 16
#define TYPED 20
#define NROWS 336
#define FF 788
#define NA 160
#define NSPLIT 6

// scratch
__device__ uint32_t g_ahi[BB * EMM * 512];                   // mention rows bf16x2 hi
__device__ uint32_t g_alo[BB * EMM * 512];                   // residual lo
__device__ float    g_rs[BB * EMM];                          // exact fp32 row sums
__device__ float    g_part[(size_t)NSPLIT * BB * EMM * HH];  // split-K partials

__device__ __forceinline__ uint32_t packbf(float lo, float hi) {
    uint32_t r;
    asm("cvt.rn.bf16x2.f32 %0, %1, %2;" : "=r"(r) : "f"(hi), "f"(lo));
    return r;
}
__device__ __forceinline__ float bflo(uint32_t p) { return __uint_as_float(p << 16); }
__device__ __forceinline__ float bfhi(uint32_t p) { return __uint_as_float(p & 0xFFFF0000u); }

// ---------------------------------------------------------------------------
// K1 "front": link [0,64) + mention rows [64,576). 576 blocks = 1 wave.
// ---------------------------------------------------------------------------
__global__ void __launch_bounds__(256) k_front(
    const float* __restrict__ att, const float* __restrict__ seq,
    const float* __restrict__ ttab, const int* __restrict__ mpos,
    const int* __restrict__ lstart, const int* __restrict__ llen,
    float* __restrict__ out)
{
    __shared__ float part[32][33];
    __shared__ float wsh[32];
    __shared__ float red[8];
    int bid = blockIdx.x, tid = threadIdx.x;

    if (bid < 64) {
        int k = bid & 15, b = bid >> 4;
        int s = lstart[b * KLNK + k] + 1;
        int len = llen[b * KLNK + k] + 1;
        int r = tid >> 3, c4 = (tid & 7) * 4;
        float a0 = 0.f, a1 = 0.f, a2 = 0.f, a3 = 0.f;
        if (r < len) {
            const float* base = att + (size_t)b * NHH * LL * LL + (size_t)(s + r) * LL + s + c4;
#pragma unroll
            for (int h = 0; h < NHH; h++) {
                const float* p = base + (size_t)h * LL * LL;
                a0 += p[0]; a1 += p[1]; a2 += p[2]; a3 += p[3];
            }
        }
        if (c4 + 0 >= len) a0 = 0.f;
        if (c4 + 1 >= len) a1 = 0.f;
        if (c4 + 2 >= len) a2 = 0.f;
        if (c4 + 3 >= len) a3 = 0.f;
        part[r][c4] = a0; part[r][c4 + 1] = a1; part[r][c4 + 2] = a2; part[r][c4 + 3] = a3;
        __syncthreads();
        if (tid < 32) {
            float sum = 0.f;
#pragma unroll
            for (int rr = 0; rr < 32; rr++) sum += part[rr][tid];   // fixed order
            wsh[tid] = sum;
        }
        __syncthreads();
        float scale = 1.f / (12.f * (float)len);
        const float* sq = seq + ((size_t)b * LL + s) * HH;
        float* o = out + ((size_t)b * NROWS + 160 + k) * FF;
        for (int f = tid; f < HH; f += 256) {
            float b0 = 0.f, b1 = 0.f, b2 = 0.f, b3 = 0.f;
#pragma unroll
            for (int c = 0; c < 32; c += 4) {
                b0 += wsh[c] * sq[(size_t)c * HH + f];
                b1 += wsh[c + 1] * sq[(size_t)(c + 1) * HH + f];
                b2 += wsh[c + 2] * sq[(size_t)(c + 2) * HH + f];
                b3 += wsh[c + 3] * sq[(size_t)(c + 3) * HH + f];
            }
            o[f] = ((b0 + b1) + (b2 + b3)) * scale;
        }
        if (tid < TYPED) o[HH + tid] = ttab[2 * TYPED + tid];
    } else {
        int i = bid - 64;
        int m = i & 127, b = i >> 7;
        int p = mpos[b * EMM + m] + 1;
        const float* rp = att + (size_t)b * NHH * LL * LL + (size_t)p * LL + tid * 4;
        float4 a = make_float4(0.f, 0.f, 0.f, 0.f);
#pragma unroll
        for (int h = 0; h < NHH; h++) {
            float4 v = *(const float4*)(rp + (size_t)h * LL * LL);
            a.x += v.x; a.y += v.y; a.z += v.z; a.w += v.w;
        }
        const float iv = 1.f / 12.f;
        a.x *= iv; a.y *= iv; a.z *= iv; a.w *= iv;
        uint32_t h1 = packbf(a.x, a.y), h2 = packbf(a.z, a.w);
        uint32_t l1 = packbf(a.x - bflo(h1), a.y - bfhi(h1));
        uint32_t l2 = packbf(a.z - bflo(h2), a.w - bfhi(h2));
        size_t u = ((size_t)b * EMM + m) * 512 + tid * 2;
        *(uint2*)&g_ahi[u] = make_uint2(h1, h2);
        *(uint2*)&g_alo[u] = make_uint2(l1, l2);

        float s = (a.x + a.y) + (a.z + a.w);
#pragma unroll
        for (int o = 16; o > 0; o >>= 1) s += __shfl_down_sync(0xffffffffu, s, o);
        if ((tid & 31) == 0) red[tid >> 5] = s;
        __syncthreads();
        if (tid == 0) {
            float t = 0.f;
#pragma unroll
            for (int w = 0; w < 8; w++) t += red[w];               // fixed order
            g_rs[b * EMM + m] = t;
        }
    }
}

// ---------------------------------------------------------------------------
// K2: WMMA bf16 3-pass split GEMM (R15-proven). Block 128m x 64h, k32 dbuf.
// Grid (12, 4, 6) = 288 blocks (2/SM). A pre-packed bf16 (pure copy).
// ---------------------------------------------------------------------------
#define LDA 40
#define LDB 72
#define CTX_SMEM 59392
__global__ void __launch_bounds__(256, 2) k_ctx_w(const float* __restrict__ seq) {
    extern __shared__ __align__(16) char dyn[];
    __nv_bfloat16* SAh = (__nv_bfloat16*)dyn;
    __nv_bfloat16* SAl = SAh + 10240;
    __nv_bfloat16* SBh = SAl + 10240;
    __nv_bfloat16* SBl = SBh + 4608;

    int hb = blockIdx.x, b = blockIdx.y, s = blockIdx.z;
    int h0 = hb * 64;
    int l_start = (s < 2) ? s * 192 : 384 + (s - 2) * 160;
    int stages = (s < 2) ? 6 : 5;
    int tid = threadIdx.x;
    int wid = tid >> 5;
    int wm = (wid & 3) * 32, wn = (wid >> 2) * 32;

    const uint32_t* ahi = g_ahi + (size_t)b * EMM * 512;
    const uint32_t* alo = g_alo + (size_t)b * EMM * 512;
    const float* seqb = seq + (size_t)b * LL * HH;

    wmma::fragment<wmma::accumulator, 16, 16, 16, float> acc[2][2];
#pragma unroll
    for (int i = 0; i < 2; i++)
#pragma unroll
        for (int j = 0; j < 2; j++) wmma::fill_fragment(acc[i][j], 0.f);

    auto loadA = [&](int buf, int k0) {
        uint32_t* ah = (uint32_t*)(SAh + buf * 5120);
        uint32_t* al = (uint32_t*)(SAl + buf * 5120);
        int kb = k0 >> 1;
#pragma unroll
        for (int it = 0; it < 4; it++) {
            int idx = tid + it * 256;
            int m = idx >> 3, u = (idx & 7) * 2;
            uint2 vh = *(const uint2*)(ahi + (size_t)m * 512 + kb + u);
            uint2 vl = *(const uint2*)(alo + (size_t)m * 512 + kb + u);
            *(uint2*)(ah + m * (LDA / 2) + u) = vh;
            *(uint2*)(al + m * (LDA / 2) + u) = vl;
        }
    };
    auto loadB = [&](int buf, int k0) {
        __nv_bfloat16* bh = SBh + buf * 2304;
        __nv_bfloat16* bl = SBl + buf * 2304;
#pragma unroll
        for (int it = 0; it < 2; it++) {
            int idx = tid + it * 256;
            int k = idx >> 4, h4 = (idx & 15) * 4;
            float4 v = *(const float4*)&seqb[(size_t)(k0 + k) * HH + h0 + h4];
            uint32_t h1 = packbf(v.x, v.y), h2 = packbf(v.z, v.w);
            uint32_t l1 = packbf(v.x - bflo(h1), v.y - bfhi(h1));
            uint32_t l2 = packbf(v.z - bflo(h2), v.w - bfhi(h2));
            *(uint2*)(bh + k * LDB + h4) = make_uint2(h1, h2);
            *(uint2*)(bl + k * LDB + h4) = make_uint2(l1, l2);
        }
    };

    loadA(0, l_start);
    loadB(0, l_start);
    __syncthreads();

    for (int st = 0; st < stages; st++) {
        int cur = st & 1;
        if (st + 1 < stages) {
            loadA(cur ^ 1, l_start + (st + 1) * 32);
            loadB(cur ^ 1, l_start + (st + 1) * 32);
        }
#pragma unroll
        for (int kk = 0; kk < 2; kk++) {
            wmma::fragment<wmma::matrix_a, 16, 16, 16, __nv_bfloat16, wmma::row_major> fah[2], fal[2];
            wmma::fragment<wmma::matrix_b, 16, 16, 16, __nv_bfloat16, wmma::row_major> fbh[2], fbl[2];
#pragma unroll
            for (int i = 0; i < 2; i++) {
                wmma::load_matrix_sync(fah[i], SAh + cur * 5120 + (wm + i * 16) * LDA + kk * 16, LDA);
                wmma::load_matrix_sync(fal[i], SAl + cur * 5120 + (wm + i * 16) * LDA + kk * 16, LDA);
            }
#pragma unroll
            for (int j = 0; j < 2; j++) {
                wmma::load_matrix_sync(fbh[j], SBh + cur * 2304 + kk * 16 * LDB + wn + j * 16, LDB);
                wmma::load_matrix_sync(fbl[j], SBl + cur * 2304 + kk * 16 * LDB + wn + j * 16, LDB);
            }
#pragma unroll
            for (int i = 0; i < 2; i++)
#pragma unroll
                for (int j = 0; j < 2; j++) {
                    wmma::mma_sync(acc[i][j], fah[i], fbh[j], acc[i][j]);
                    wmma::mma_sync(acc[i][j], fal[i], fbh[j], acc[i][j]);
                    wmma::mma_sync(acc[i][j], fah[i], fbl[j], acc[i][j]);
                }
        }
        __syncthreads();
    }

#pragma unroll
    for (int i = 0; i < 2; i++)
#pragma unroll
        for (int j = 0; j < 2; j++) {
            float* dst = g_part + (((size_t)s * BB + b) * EMM + wm + i * 16) * HH
                       + h0 + wn + j * 16;
            wmma::store_matrix_sync(dst, acc[i][j], HH, wmma::mem_row_major);
        }
}

// ---------------------------------------------------------------------------
// K3 "tail": split-K epilogue [0,640) + node bank [640,1280). Light kernel.
// ---------------------------------------------------------------------------
__global__ void __launch_bounds__(256) k_tail(
    const float* __restrict__ seq, const float* __restrict__ ttab,
    const int* __restrict__ mpos, float* __restrict__ out)
{
    int bid = blockIdx.x, tid = threadIdx.x;
    const size_t SP = (size_t)BB * EMM * HH;

    if (bid < 640) {
        // --------------- split-K epilogue: ctx rows 176..335 ----------------
        int r = bid % NA, b = bid / NA;
        float* o = out + ((size_t)b * NROWS + 176 + r) * FF;
        if (tid < 192) {
            int f = tid * 4;
            float4 v = make_float4(0.f, 0.f, 0.f, 0.f);
            float scale;
            if (r < EE) {
#pragma unroll
                for (int s = 0; s < NSPLIT; s++)
#pragma unroll
                    for (int mp = 0; mp < MPE; mp++) {
                        const float* gp = g_part + s * SP + ((size_t)b * EMM + r * MPE + mp) * HH + f;
                        float4 p = *(const float4*)gp;
                        v.x += p.x; v.y += p.y; v.z += p.z; v.w += p.w;
                    }
                const float* rs = g_rs + b * EMM + r * MPE;
                scale = 1.f / ((((rs[0] + rs[1]) + rs[2]) + rs[3]) + 4e-5f);
            } else {
                int m = r - EE;
#pragma unroll
                for (int s = 0; s < NSPLIT; s++) {
                    const float* gp = g_part + s * SP + ((size_t)b * EMM + m) * HH + f;
                    float4 p = *(const float4*)gp;
                    v.x += p.x; v.y += p.y; v.z += p.z; v.w += p.w;
                }
                scale = 1.f / (g_rs[b * EMM + m] + 1e-5f);
            }
            *(float4*)(o + f) = make_float4(v.x * scale, v.y * scale, v.z * scale, v.w * scale);
        } else if (tid < 192 + TYPED) {
            o[HH + tid - 192] = 0.f;
        }
    } else {
        // --------------------- node bank rows 0..159 ------------------------
        int i = bid - 640;
        int r2 = i % 160, b = i / 160;
        float* o = out + ((size_t)b * NROWS + r2) * FF;
        if (r2 < EE) {
            const int* mp = mpos + (b * EE + r2) * MPE;
            int p0 = mp[0] + 1, p1 = mp[1] + 1, p2 = mp[2] + 1, p3 = mp[3] + 1;
            if (tid < 192) {
                int f = tid * 4;
                float4 x0 = *(const float4*)(seq + ((size_t)b * LL + p0) * HH + f);
                float4 x1 = *(const float4*)(seq + ((size_t)b * LL + p1) * HH + f);
                float4 x2 = *(const float4*)(seq + ((size_t)b * LL + p2) * HH + f);
                float4 x3 = *(const float4*)(seq + ((size_t)b * LL + p3) * HH + f);
                float4 res;
                float m0 = fmaxf(fmaxf(x0.x, x1.x), fmaxf(x2.x, x3.x));
                res.x = m0 + logf(expf(x0.x-m0)+expf(x1.x-m0)+expf(x2.x-m0)+expf(x3.x-m0));
                float m1 = fmaxf(fmaxf(x0.y, x1.y), fmaxf(x2.y, x3.y));
                res.y = m1 + logf(expf(x0.y-m1)+expf(x1.y-m1)+expf(x2.y-m1)+expf(x3.y-m1));
                float m2 = fmaxf(fmaxf(x0.z, x1.z), fmaxf(x2.z, x3.z));
                res.z = m2 + logf(expf(x0.z-m2)+expf(x1.z-m2)+expf(x2.z-m2)+expf(x3.z-m2));
                float m3 = fmaxf(fmaxf(x0.w, x1.w), fmaxf(x2.w, x3.w));
                res.w = m3 + logf(expf(x0.w-m3)+expf(x1.w-m3)+expf(x2.w-m3)+expf(x3.w-m3));
                *(float4*)(o + f) = res;
            } else if (tid < 192 + TYPED) {
                o[HH + tid - 192] = ttab[tid - 192];
            }
        } else {
            int m = r2 - EE;
            int p = mpos[b * EMM + m] + 1;
            if (tid < 192)
                *(float4*)(o + tid * 4) = *(const float4*)(seq + ((size_t)b * LL + p) * HH + tid * 4);
            else if (tid < 192 + TYPED)
                o[HH + tid - 192] = ttab[TYPED + tid - 192];
        }
    }
}

// ---------------------------------------------------------------------------
extern "C" void kernel_launch(void* const* d_in, const int* in_sizes, int n_in,
                              void* d_out, int out_size) {
    const float* seq    = (const float*)d_in[0];
    const float* att    = (const float*)d_in[1];
    const float* ttab   = (const float*)d_in[2];
    const int*   mpos   = (const int*)d_in[3];
    const int*   lstart = (const int*)d_in[4];
    const int*   llen   = (const int*)d_in[5];
    float* out = (float*)d_out;

    cudaFuncSetAttribute(k_ctx_w, cudaFuncAttributeMaxDynamicSharedMemorySize,
                         CTX_SMEM);

    k_front<<<64 + 512, 256>>>(att, seq, ttab, mpos, lstart, llen, out);
    k_ctx_w<<<dim3(12, BB, NSPLIT), 256, CTX_SMEM>>>(seq);
    k_tail<<<640 + 640, 256>>>(seq, ttab, mpos, out);
}